// round 13
// baseline (speedup 1.0000x reference)
#include <cuda_runtime.h>
#include <cuda_fp16.h>
#include <math.h>
#include <stdint.h>

// Problem constants
#define NN 50000
#define EE 800000

#define SCAN_B 256
#define SCAN_G ((NN + SCAN_B - 1) / SCAN_B)   // 196
#define TOTW (256 * 128 + 128 * 128 + 64 * 64)  // 53248
#define INIT_G ((TOTW + SCAN_B - 1) / SCAN_B)

// ---------------- scratch (device globals; no allocation allowed) ------------
__device__ __align__(16) __half g_xh[(size_t)NN * 128];   // x in half
__device__ __align__(16) __half g_xlr[(size_t)NN * 256];  // [xl|xr] half
__device__ __align__(16) __half g_h[(size_t)NN * 128];    // relu(sage1), half
__device__ __align__(16) __half g_hlr[(size_t)NN * 128];  // [hl|hr] half
__device__ __align__(16) __half g_h3[(size_t)NN * 64];    // softmax out, half
__device__ __align__(16) __half g_xw[(size_t)NN * 64];    // h3 @ Wg (half)
__device__ __align__(16) __half g_wb1[256 * 128];
__device__ __align__(16) __half g_wb2[128 * 128];
__device__ __align__(16) __half g_wbg[64 * 64];
__device__ int   g_deg[NN];
__device__ int   g_off[NN + 1];
__device__ int   g_cur[NN];
__device__ int   g_csr[EE];
__device__ float g_dinv[NN];
__device__ int   g_is64;
__device__ int   g_part[SCAN_G];
__device__ int   g_poff[SCAN_G];

__device__ __forceinline__ const __half* pickA(int s) {
    switch (s) {
        case 0:  return g_xh;
        case 1:  return g_h;
        default: return g_h3;
    }
}
__device__ __forceinline__ const __half* pickB(int s) {
    switch (s) {
        case 0:  return g_wb1;
        case 1:  return g_wb2;
        default: return g_wbg;
    }
}
__device__ __forceinline__ __half* pickC(int s) {
    switch (s) {
        case 0:  return g_xlr;
        case 1:  return g_hlr;
        default: return g_xw;
    }
}

__device__ __forceinline__ int edge_at(const void* ei, size_t idx) {
    if (g_is64) return (int)((const long long*)ei)[idx];
    return ((const int*)ei)[idx];
}

__device__ __forceinline__ void ldsm_x4(uint32_t& r0, uint32_t& r1,
                                        uint32_t& r2, uint32_t& r3,
                                        uint32_t addr) {
    asm volatile(
        "ldmatrix.sync.aligned.m8n8.x4.shared.b16 {%0,%1,%2,%3}, [%4];"
        : "=r"(r0), "=r"(r1), "=r"(r2), "=r"(r3)
        : "r"(addr));
}

__device__ __forceinline__ void cp16(uint32_t saddr, const void* gptr) {
    asm volatile("cp.async.cg.shared.global [%0], [%1], 16;" ::"r"(saddr),
                 "l"(gptr));
}
__device__ __forceinline__ void cp_commit() {
    asm volatile("cp.async.commit_group;");
}
__device__ __forceinline__ void cp_wait_n(int n) {
    switch (n) {
        case 0: asm volatile("cp.async.wait_group 0;"); break;
        case 1: asm volatile("cp.async.wait_group 1;"); break;
        case 2: asm volatile("cp.async.wait_group 2;"); break;
        case 3: asm volatile("cp.async.wait_group 3;"); break;
        case 4: asm volatile("cp.async.wait_group 4;"); break;
        case 5: asm volatile("cp.async.wait_group 5;"); break;
        case 6: asm volatile("cp.async.wait_group 6;"); break;
        default: asm volatile("cp.async.wait_group 7;"); break;
    }
}

// ---------------- init: zero deg + dtype detect + weight convert -------------
__global__ void k_init(const void* ei, const float* __restrict__ W1l,
                       const float* __restrict__ W1r,
                       const float* __restrict__ W2l,
                       const float* __restrict__ W2r,
                       const float* __restrict__ Wg) {
    int idx = blockIdx.x * blockDim.x + threadIdx.x;
    if (idx < NN) g_deg[idx] = 0;
    if (idx < 256 * 128) {
        int n = idx >> 7, k = idx & 127;
        float v = (n < 128) ? W1l[k * 128 + n] : W1r[k * 128 + (n - 128)];
        g_wb1[idx] = __float2half_rn(v);
    } else if (idx < 256 * 128 + 128 * 128) {
        int j = idx - 256 * 128;
        int n = j >> 7, k = j & 127;
        float v = (n < 64) ? W2l[k * 64 + n] : W2r[k * 64 + (n - 64)];
        g_wb2[j] = __float2half_rn(v);
    } else if (idx < TOTW) {
        int j = idx - (256 * 128 + 128 * 128);
        int n = j >> 6, k = j & 63;
        g_wbg[j] = __float2half_rn(Wg[k * 64 + n]);
    }
    if (blockIdx.x == 0) {
        __shared__ int bad;
        if (threadIdx.x == 0) bad = 0;
        __syncthreads();
        const long long* p = (const long long*)ei;
        for (int k = threadIdx.x; k < 2048; k += SCAN_B) {
            long long v = p[k];
            if (v < 0 || v >= NN) bad = 1;  // benign race
        }
        __syncthreads();
        if (threadIdx.x == 0) g_is64 = bad ? 0 : 1;
    }
}

// ---------------- convert x to half ------------------------------------------
__global__ void k_cvtx(const float* __restrict__ x) {
    int idx = blockIdx.x * blockDim.x + threadIdx.x;  // uint4 of 8 halves
    const int total = NN * 128 / 8;
    if (idx < total) {
        const float4* p = (const float4*)x + (size_t)idx * 2;
        float4 f0 = p[0], f1 = p[1];
        __half2 h[4] = {__floats2half2_rn(f0.x, f0.y),
                        __floats2half2_rn(f0.z, f0.w),
                        __floats2half2_rn(f1.x, f1.y),
                        __floats2half2_rn(f1.z, f1.w)};
        ((uint4*)g_xh)[idx] = *(uint4*)h;
    }
}

// ---------------- CSR build --------------------------------------------------
__global__ void k_hist(const void* __restrict__ ei) {
    int e = blockIdx.x * blockDim.x + threadIdx.x;
    if (e < EE) {
        int d = edge_at(ei, (size_t)EE + e);
        if ((unsigned)d < NN) atomicAdd(&g_deg[d], 1);
    }
}

__global__ void k_scan_a() {
    __shared__ int s[SCAN_B];
    int t = threadIdx.x;
    int i = blockIdx.x * SCAN_B + t;
    s[t] = (i < NN) ? g_deg[i] : 0;
    __syncthreads();
#pragma unroll
    for (int o = SCAN_B / 2; o > 0; o >>= 1) {
        if (t < o) s[t] += s[t + o];
        __syncthreads();
    }
    if (t == 0) g_part[blockIdx.x] = s[0];
}

__global__ void k_scan_b() {
    __shared__ int s[SCAN_B];
    int t = threadIdx.x;
    int v = (t < SCAN_G) ? g_part[t] : 0;
    s[t] = v;
    __syncthreads();
#pragma unroll
    for (int o = 1; o < SCAN_B; o <<= 1) {
        int u = (t >= o) ? s[t - o] : 0;
        __syncthreads();
        s[t] += u;
        __syncthreads();
    }
    if (t < SCAN_G) g_poff[t] = s[t] - v;
    if (t == SCAN_B - 1) g_off[NN] = s[SCAN_B - 1];
}

__global__ void k_scan_c() {
    __shared__ int s[SCAN_B];
    int t = threadIdx.x;
    int i = blockIdx.x * SCAN_B + t;
    int v = (i < NN) ? g_deg[i] : 0;
    s[t] = v;
    __syncthreads();
#pragma unroll
    for (int o = 1; o < SCAN_B; o <<= 1) {
        int u = (t >= o) ? s[t - o] : 0;
        __syncthreads();
        s[t] += u;
        __syncthreads();
    }
    if (i < NN) {
        int off = g_poff[blockIdx.x] + s[t] - v;
        g_off[i] = off;
        g_cur[i] = off;
        g_dinv[i] = rsqrtf((float)(v + 1));
    }
}

__global__ void k_scatter(const void* __restrict__ ei) {
    int e = blockIdx.x * blockDim.x + threadIdx.x;
    if (e < EE) {
        int d = edge_at(ei, (size_t)EE + e);
        int srcv = edge_at(ei, (size_t)e);
        if ((unsigned)d < NN && (unsigned)srcv < NN) {
            int pos = atomicAdd(&g_cur[d], 1);
            if ((unsigned)pos < EE) g_csr[pos] = srcv;
        }
    }
}

// ---------------- fp16 HMMA GEMM: cp.async chunked pipeline ------------------
// C[m, col0+n] = A[m,:K] @ Wh[col0+n][:K]^T, half in/out. KK in {64,128}.
// BM=128. 8 warps: warpM=w&3 (32 rows), warpN=w>>2 (NB/2 cols each).
// All k-chunks issued up-front as cp.async commit-groups; consumed in order.
#define LDS_H 136  // row stride in halves (272 B): conflict-free for ldmatrix
template <int NB, int KK>
__global__ void __launch_bounds__(256) k_gemm(int asel, int bsel, int csel,
                                              int M, int ldc) {
    constexpr int NCH = KK / 16;  // 8 or 4 chunks
    constexpr int FN = NB / 16;
    extern __shared__ __half smem[];
    __half* As = smem;                  // [128][LDS_H]
    __half* Bs = smem + 128 * LDS_H;    // [NB][LDS_H]
    const __half* __restrict__ A = pickA(asel);
    const __half* __restrict__ Wh = pickB(bsel);
    const int col0 = blockIdx.y * NB;
    const int row0 = blockIdx.x * 128;

    const int tid = threadIdx.x;
    const int lane = tid & 31;
    const int w = tid >> 5;
    const int warpM = w & 3;
    const int warpN = w >> 2;
    const int grp = lane >> 2;
    const int qid = lane & 3;

    // issue all k-chunks up-front (one commit-group per chunk)
    {
        const int r = tid >> 1;          // 0..127
        const int u = tid & 1;           // uint4 within 16-half chunk
        const int gr = min(row0 + r, M - 1);  // OOB rows clamp (never stored)
        const size_t abase = (size_t)gr * KK + u * 8;
        uint32_t sa = (uint32_t)__cvta_generic_to_shared(As + r * LDS_H + u * 8);
#pragma unroll
        for (int c = 0; c < NCH; c++) {
            cp16(sa + c * 32, A + abase + c * 16);
            if (NB == 128) {
                cp16((uint32_t)__cvta_generic_to_shared(Bs + r * LDS_H + u * 8) +
                         c * 32,
                     Wh + (size_t)(col0 + r) * KK + u * 8 + c * 16);
            } else {
                if (tid < 128)
                    cp16((uint32_t)__cvta_generic_to_shared(Bs + r * LDS_H +
                                                            u * 8) +
                             c * 32,
                         Wh + (size_t)(col0 + r) * KK + u * 8 + c * 16);
            }
            cp_commit();
        }
    }

    const int arow = warpM * 32 + (lane & 7) + ((lane >> 3) & 1) * 8;
    const int acol = (lane >> 4) * 8;
    const int brow = warpN * (NB / 2) + ((lane >> 4)) * 8 + (lane & 7);
    const int bcol = ((lane >> 3) & 1) * 8;

    float acc[2][FN][4];
#pragma unroll
    for (int s = 0; s < 2; s++)
#pragma unroll
        for (int f = 0; f < FN; f++)
#pragma unroll
            for (int j = 0; j < 4; j++) acc[s][f][j] = 0.f;

#pragma unroll
    for (int it = 0; it < NCH; it++) {
        cp_wait_n(NCH - 1 - it);  // chunks 0..it complete (this thread)
        __syncthreads();          // ... and all threads'
        const int ko = it * 16;
        uint32_t av[2][4], bv[FN][2];
#pragma unroll
        for (int s = 0; s < 2; s++) {
            uint32_t addrA = (uint32_t)__cvta_generic_to_shared(
                As + (arow + s * 16) * LDS_H + acol + ko);
            ldsm_x4(av[s][0], av[s][1], av[s][2], av[s][3], addrA);
        }
#pragma unroll
        for (int p = 0; p < FN / 2; p++) {
            uint32_t addrB = (uint32_t)__cvta_generic_to_shared(
                Bs + (brow + p * 16) * LDS_H + bcol + ko);
            ldsm_x4(bv[2 * p][0], bv[2 * p][1], bv[2 * p + 1][0],
                    bv[2 * p + 1][1], addrB);
        }
#pragma unroll
        for (int s = 0; s < 2; s++)
#pragma unroll
            for (int f = 0; f < FN; f++) {
                asm volatile(
                    "mma.sync.aligned.m16n8k16.row.col.f32.f16.f16.f32 "
                    "{%0,%1,%2,%3}, {%4,%5,%6,%7}, {%8,%9}, {%0,%1,%2,%3};\n"
                    : "+f"(acc[s][f][0]), "+f"(acc[s][f][1]),
                      "+f"(acc[s][f][2]), "+f"(acc[s][f][3])
                    : "r"(av[s][0]), "r"(av[s][1]), "r"(av[s][2]),
                      "r"(av[s][3]), "r"(bv[f][0]), "r"(bv[f][1]));
            }
    }

    __half* Ch = pickC(csel);
#pragma unroll
    for (int s = 0; s < 2; s++) {
        int r0 = row0 + warpM * 32 + s * 16 + grp;
#pragma unroll
        for (int f = 0; f < FN; f++) {
            int c = col0 + warpN * (NB / 2) + f * 8 + 2 * qid;
            if (r0 < M)
                *(__half2*)(Ch + (size_t)r0 * ldc + c) =
                    __floats2half2_rn(acc[s][f][0], acc[s][f][1]);
            if (r0 + 8 < M)
                *(__half2*)(Ch + (size_t)(r0 + 8) * ldc + c) =
                    __floats2half2_rn(acc[s][f][2], acc[s][f][3]);
        }
    }
}

// ---------------- SAGE layer 1 aggregation + epilogue (relu) -----------------
// block (32,8): warp per node; lane t covers cols 4t..4t+3; unroll 8
__global__ void k_agg1(const float* __restrict__ b1l) {
    int i = blockIdx.x * 8 + threadIdx.y;
    if (i >= NN) return;
    int t = threadIdx.x;  // 0..31
    int off = g_off[i];
    int deg = g_deg[i];
    const uint2* base = (const uint2*)g_xlr;  // row = 64 uint2 (256 halves)
    float4 a0 = {0, 0, 0, 0}, a1 = a0, a2 = a0, a3 = a0;
    int j = 0;
    for (; j + 7 < deg; j += 8) {
        uint2 u0 = base[(size_t)g_csr[off + j] * 64 + t];
        uint2 u1 = base[(size_t)g_csr[off + j + 1] * 64 + t];
        uint2 u2 = base[(size_t)g_csr[off + j + 2] * 64 + t];
        uint2 u3 = base[(size_t)g_csr[off + j + 3] * 64 + t];
        uint2 u4 = base[(size_t)g_csr[off + j + 4] * 64 + t];
        uint2 u5 = base[(size_t)g_csr[off + j + 5] * 64 + t];
        uint2 u6 = base[(size_t)g_csr[off + j + 6] * 64 + t];
        uint2 u7 = base[(size_t)g_csr[off + j + 7] * 64 + t];
        float2 p, q;
        p = __half22float2(*(__half2*)&u0.x); q = __half22float2(*(__half2*)&u0.y);
        a0.x += p.x; a0.y += p.y; a0.z += q.x; a0.w += q.y;
        p = __half22float2(*(__half2*)&u1.x); q = __half22float2(*(__half2*)&u1.y);
        a1.x += p.x; a1.y += p.y; a1.z += q.x; a1.w += q.y;
        p = __half22float2(*(__half2*)&u2.x); q = __half22float2(*(__half2*)&u2.y);
        a2.x += p.x; a2.y += p.y; a2.z += q.x; a2.w += q.y;
        p = __half22float2(*(__half2*)&u3.x); q = __half22float2(*(__half2*)&u3.y);
        a3.x += p.x; a3.y += p.y; a3.z += q.x; a3.w += q.y;
        p = __half22float2(*(__half2*)&u4.x); q = __half22float2(*(__half2*)&u4.y);
        a0.x += p.x; a0.y += p.y; a0.z += q.x; a0.w += q.y;
        p = __half22float2(*(__half2*)&u5.x); q = __half22float2(*(__half2*)&u5.y);
        a1.x += p.x; a1.y += p.y; a1.z += q.x; a1.w += q.y;
        p = __half22float2(*(__half2*)&u6.x); q = __half22float2(*(__half2*)&u6.y);
        a2.x += p.x; a2.y += p.y; a2.z += q.x; a2.w += q.y;
        p = __half22float2(*(__half2*)&u7.x); q = __half22float2(*(__half2*)&u7.y);
        a3.x += p.x; a3.y += p.y; a3.z += q.x; a3.w += q.y;
    }
    for (; j < deg; j++) {
        uint2 u = base[(size_t)g_csr[off + j] * 64 + t];
        float2 p = __half22float2(*(__half2*)&u.x);
        float2 q = __half22float2(*(__half2*)&u.y);
        a0.x += p.x; a0.y += p.y; a0.z += q.x; a0.w += q.y;
    }
    float4 s;
    s.x = (a0.x + a1.x) + (a2.x + a3.x);
    s.y = (a0.y + a1.y) + (a2.y + a3.y);
    s.z = (a0.z + a1.z) + (a2.z + a3.z);
    s.w = (a0.w + a1.w) + (a2.w + a3.w);
    float inv = 1.f / fmaxf((float)deg, 1.f);
    uint2 ur = base[(size_t)i * 64 + 32 + t];
    float2 rp = __half22float2(*(__half2*)&ur.x);
    float2 rq = __half22float2(*(__half2*)&ur.y);
    float4 b = *(const float4*)(b1l + 4 * t);
    __half2 o0 = __floats2half2_rn(fmaxf(s.x * inv + b.x + rp.x, 0.f),
                                   fmaxf(s.y * inv + b.y + rp.y, 0.f));
    __half2 o1 = __floats2half2_rn(fmaxf(s.z * inv + b.z + rq.x, 0.f),
                                   fmaxf(s.w * inv + b.w + rq.y, 0.f));
    uint2 u;
    u.x = *(uint32_t*)&o0;
    u.y = *(uint32_t*)&o1;
    *(uint2*)(g_h + (size_t)i * 128 + 4 * t) = u;
}

// ---------------- SAGE layer 2 aggregation + softmax epilogue ----------------
__global__ void k_agg2(const float* __restrict__ b2l) {
    int i = blockIdx.x * 8 + threadIdx.y;
    if (i >= NN) return;
    int t = threadIdx.x;  // 0..31
    int off = g_off[i];
    int deg = g_deg[i];
    const __half2* base = (const __half2*)g_hlr;  // row stride 64 half2
    float2 a0 = {0, 0}, a1 = {0, 0}, a2 = {0, 0}, a3 = {0, 0};
    float2 a4 = {0, 0}, a5 = {0, 0}, a6 = {0, 0}, a7 = {0, 0};
    int j = 0;
    for (; j + 7 < deg; j += 8) {
        float2 v0 = __half22float2(base[(size_t)g_csr[off + j] * 64 + t]);
        float2 v1 = __half22float2(base[(size_t)g_csr[off + j + 1] * 64 + t]);
        float2 v2 = __half22float2(base[(size_t)g_csr[off + j + 2] * 64 + t]);
        float2 v3 = __half22float2(base[(size_t)g_csr[off + j + 3] * 64 + t]);
        float2 v4 = __half22float2(base[(size_t)g_csr[off + j + 4] * 64 + t]);
        float2 v5 = __half22float2(base[(size_t)g_csr[off + j + 5] * 64 + t]);
        float2 v6 = __half22float2(base[(size_t)g_csr[off + j + 6] * 64 + t]);
        float2 v7 = __half22float2(base[(size_t)g_csr[off + j + 7] * 64 + t]);
        a0.x += v0.x; a0.y += v0.y;  a1.x += v1.x; a1.y += v1.y;
        a2.x += v2.x; a2.y += v2.y;  a3.x += v3.x; a3.y += v3.y;
        a4.x += v4.x; a4.y += v4.y;  a5.x += v5.x; a5.y += v5.y;
        a6.x += v6.x; a6.y += v6.y;  a7.x += v7.x; a7.y += v7.y;
    }
    for (; j < deg; j++) {
        float2 v = __half22float2(base[(size_t)g_csr[off + j] * 64 + t]);
        a0.x += v.x; a0.y += v.y;
    }
    float sx = ((a0.x + a1.x) + (a2.x + a3.x)) + ((a4.x + a5.x) + (a6.x + a7.x));
    float sy = ((a0.y + a1.y) + (a2.y + a3.y)) + ((a4.y + a5.y) + (a6.y + a7.y));
    float inv = 1.f / fmaxf((float)deg, 1.f);
    float2 hr = __half22float2(base[(size_t)i * 64 + 32 + t]);
    float v0 = sx * inv + b2l[2 * t] + hr.x;
    float v1 = sy * inv + b2l[2 * t + 1] + hr.y;
    float m = fmaxf(v0, v1);
#pragma unroll
    for (int o = 16; o > 0; o >>= 1) m = fmaxf(m, __shfl_xor_sync(0xffffffffu, m, o));
    float e0 = __expf(v0 - m), e1 = __expf(v1 - m);
    float s = e0 + e1;
#pragma unroll
    for (int o = 16; o > 0; o >>= 1) s += __shfl_xor_sync(0xffffffffu, s, o);
    float rs = 1.f / s;
    *(__half2*)(g_h3 + (size_t)i * 64 + 2 * t) =
        __floats2half2_rn(e0 * rs, e1 * rs);
}

// ---------------- GCN aggregation (writes final output) ----------------------
__global__ void k_agg3(const float* __restrict__ bg, float* __restrict__ out) {
    int i = blockIdx.x * 8 + threadIdx.y;
    if (i >= NN) return;
    int t = threadIdx.x;  // 0..31
    int off = g_off[i];
    int deg = g_deg[i];
    float di = g_dinv[i];
    const __half2* base = (const __half2*)g_xw;  // row stride 32 half2
    float2 a0 = {0, 0}, a1 = {0, 0}, a2 = {0, 0}, a3 = {0, 0};
    float2 a4 = {0, 0}, a5 = {0, 0}, a6 = {0, 0}, a7 = {0, 0};
    int j = 0;
    for (; j + 7 < deg; j += 8) {
        int s0 = g_csr[off + j],     s1 = g_csr[off + j + 1];
        int s2 = g_csr[off + j + 2], s3 = g_csr[off + j + 3];
        int s4 = g_csr[off + j + 4], s5 = g_csr[off + j + 5];
        int s6 = g_csr[off + j + 6], s7 = g_csr[off + j + 7];
        float d0 = g_dinv[s0], d1 = g_dinv[s1], d2 = g_dinv[s2], d3 = g_dinv[s3];
        float d4 = g_dinv[s4], d5 = g_dinv[s5], d6 = g_dinv[s6], d7 = g_dinv[s7];
        float2 v0 = __half22float2(base[(size_t)s0 * 32 + t]);
        float2 v1 = __half22float2(base[(size_t)s1 * 32 + t]);
        float2 v2 = __half22float2(base[(size_t)s2 * 32 + t]);
        float2 v3 = __half22float2(base[(size_t)s3 * 32 + t]);
        float2 v4 = __half22float2(base[(size_t)s4 * 32 + t]);
        float2 v5 = __half22float2(base[(size_t)s5 * 32 + t]);
        float2 v6 = __half22float2(base[(size_t)s6 * 32 + t]);
        float2 v7 = __half22float2(base[(size_t)s7 * 32 + t]);
        a0.x += v0.x * d0; a0.y += v0.y * d0;
        a1.x += v1.x * d1; a1.y += v1.y * d1;
        a2.x += v2.x * d2; a2.y += v2.y * d2;
        a3.x += v3.x * d3; a3.y += v3.y * d3;
        a4.x += v4.x * d4; a4.y += v4.y * d4;
        a5.x += v5.x * d5; a5.y += v5.y * d5;
        a6.x += v6.x * d6; a6.y += v6.y * d6;
        a7.x += v7.x * d7; a7.y += v7.y * d7;
    }
    for (; j < deg; j++) {
        int s = g_csr[off + j];
        float d = g_dinv[s];
        float2 v = __half22float2(base[(size_t)s * 32 + t]);
        a0.x += v.x * d; a0.y += v.y * d;
    }
    float2 self = __half22float2(base[(size_t)i * 32 + t]);
    float sx = ((a0.x + a1.x) + (a2.x + a3.x)) + ((a4.x + a5.x) + (a6.x + a7.x)) +
               self.x * di;
    float sy = ((a0.y + a1.y) + (a2.y + a3.y)) + ((a4.y + a5.y) + (a6.y + a7.y)) +
               self.y * di;
    float ox = sx * di + bg[2 * t];
    float oy = sy * di + bg[2 * t + 1];
    *(float2*)(out + (size_t)i * 64 + 2 * t) = make_float2(ox, oy);
}

// ---------------- launch -----------------------------------------------------
extern "C" void kernel_launch(void* const* d_in, const int* in_sizes, int n_in,
                              void* d_out, int out_size) {
    const float* x = (const float*)d_in[0];
    const void* ei = d_in[1];
    const float* W1l = (const float*)d_in[2];
    const float* b1l = (const float*)d_in[3];
    const float* W1r = (const float*)d_in[4];
    const float* W2l = (const float*)d_in[5];
    const float* b2l = (const float*)d_in[6];
    const float* W2r = (const float*)d_in[7];
    const float* Wg = (const float*)d_in[8];
    const float* bg = (const float*)d_in[9];
    float* out = (float*)d_out;

    const int smem128 = (128 + 128) * LDS_H * 2;  // 69632 B
    const int smem64 = (128 + 64) * LDS_H * 2;    // 52224 B
    cudaFuncSetAttribute(k_gemm<128, 128>,
                         cudaFuncAttributeMaxDynamicSharedMemorySize, smem128);
    cudaFuncSetAttribute(k_gemm<64, 64>,
                         cudaFuncAttributeMaxDynamicSharedMemorySize, smem64);

    k_init<<<INIT_G, SCAN_B>>>(ei, W1l, W1r, W2l, W2r, Wg);
    k_cvtx<<<(NN * 128 / 8 + 255) / 256, 256>>>(x);
    k_hist<<<(EE + 255) / 256, 256>>>(ei);
    // slot 4: gemm1 (ncu capture): [xl|xr] = xh @ [W1l,W1r], BN=128
    dim3 g1((NN + 127) / 128, 2);
    k_gemm<128, 128><<<g1, 256, smem128>>>(0, 0, 0, NN, 256);
    k_scan_a<<<SCAN_G, SCAN_B>>>();
    k_scan_b<<<1, SCAN_B>>>();
    k_scan_c<<<SCAN_G, SCAN_B>>>();
    k_scatter<<<(EE + 255) / 256, 256>>>(ei);
    k_agg1<<<(NN + 7) / 8, dim3(32, 8)>>>(b1l);
    dim3 g2((NN + 127) / 128, 1);
    k_gemm<128, 128><<<g2, 256, smem128>>>(1, 1, 1, NN, 128);
    k_agg2<<<(NN + 7) / 8, dim3(32, 8)>>>(b2l);
    dim3 g3((NN + 127) / 128, 1);
    k_gemm<64, 64><<<g3, 256, smem64>>>(2, 2, 2, NN, 64);
    k_agg3<<<(NN + 7) / 8, dim3(32, 8)>>>(bg, out);
}

// round 14
// speedup vs baseline: 1.0696x; 1.0696x over previous
#include <cuda_runtime.h>
#include <cuda_fp16.h>
#include <math.h>
#include <stdint.h>

// Problem constants
#define NN 50000
#define EE 800000

#define SCAN_B 256
#define SCAN_G ((NN + SCAN_B - 1) / SCAN_B)   // 196
#define TOTW (256 * 128 + 128 * 128 + 64 * 64)  // 53248
#define INIT_G ((TOTW + SCAN_B - 1) / SCAN_B)

// ---------------- scratch (device globals; no allocation allowed) ------------
__device__ __align__(16) __half g_xlr[(size_t)NN * 256];  // [xl|xr] half
__device__ __align__(16) __half g_h[(size_t)NN * 128];    // relu(sage1), half
__device__ __align__(16) __half g_hlr[(size_t)NN * 128];  // [hl|hr] half
__device__ __align__(16) __half g_h3[(size_t)NN * 64];    // softmax out, half
__device__ __align__(16) __half g_xw[(size_t)NN * 64];    // h3 @ Wg (half)
__device__ __align__(16) __half g_wb1[256 * 128];
__device__ __align__(16) __half g_wb2[128 * 128];
__device__ __align__(16) __half g_wbg[64 * 64];
__device__ int   g_deg[NN];
__device__ int   g_off[NN + 1];
__device__ int   g_cur[NN];
__device__ int   g_csr[EE];
__device__ float g_dinv[NN];
__device__ int   g_is64;
__device__ int   g_part[SCAN_G];
__device__ int   g_poff[SCAN_G];

__device__ __forceinline__ const __half* pickA(int s) {
    switch (s) {
        case 2:  return g_h3;
        default: return g_h;
    }
}
__device__ __forceinline__ const __half* pickB(int s) {
    switch (s) {
        case 0:  return g_wb1;
        case 1:  return g_wb2;
        default: return g_wbg;
    }
}
__device__ __forceinline__ __half* pickC(int s) {
    switch (s) {
        case 0:  return g_xlr;
        case 1:  return g_hlr;
        default: return g_xw;
    }
}

__device__ __forceinline__ int edge_at(const void* ei, size_t idx) {
    if (g_is64) return (int)((const long long*)ei)[idx];
    return ((const int*)ei)[idx];
}

__device__ __forceinline__ void ldsm_x4(uint32_t& r0, uint32_t& r1,
                                        uint32_t& r2, uint32_t& r3,
                                        uint32_t addr) {
    asm volatile(
        "ldmatrix.sync.aligned.m8n8.x4.shared.b16 {%0,%1,%2,%3}, [%4];"
        : "=r"(r0), "=r"(r1), "=r"(r2), "=r"(r3)
        : "r"(addr));
}

// ---------------- init: zero deg + dtype detect + weight convert -------------
__global__ void k_init(const void* ei, const float* __restrict__ W1l,
                       const float* __restrict__ W1r,
                       const float* __restrict__ W2l,
                       const float* __restrict__ W2r,
                       const float* __restrict__ Wg) {
    int idx = blockIdx.x * blockDim.x + threadIdx.x;
    if (idx < NN) g_deg[idx] = 0;
    if (idx < 256 * 128) {
        int n = idx >> 7, k = idx & 127;
        float v = (n < 128) ? W1l[k * 128 + n] : W1r[k * 128 + (n - 128)];
        g_wb1[idx] = __float2half_rn(v);
    } else if (idx < 256 * 128 + 128 * 128) {
        int j = idx - 256 * 128;
        int n = j >> 7, k = j & 127;
        float v = (n < 64) ? W2l[k * 64 + n] : W2r[k * 64 + (n - 64)];
        g_wb2[j] = __float2half_rn(v);
    } else if (idx < TOTW) {
        int j = idx - (256 * 128 + 128 * 128);
        int n = j >> 6, k = j & 63;
        g_wbg[j] = __float2half_rn(Wg[k * 64 + n]);
    }
    if (blockIdx.x == 0) {
        __shared__ int bad;
        if (threadIdx.x == 0) bad = 0;
        __syncthreads();
        const long long* p = (const long long*)ei;
        for (int k = threadIdx.x; k < 2048; k += SCAN_B) {
            long long v = p[k];
            if (v < 0 || v >= NN) bad = 1;  // benign race
        }
        __syncthreads();
        if (threadIdx.x == 0) g_is64 = bad ? 0 : 1;
    }
}

// ---------------- CSR build --------------------------------------------------
__global__ void k_hist(const void* __restrict__ ei) {
    int e = blockIdx.x * blockDim.x + threadIdx.x;
    if (e < EE) {
        int d = edge_at(ei, (size_t)EE + e);
        if ((unsigned)d < NN) atomicAdd(&g_deg[d], 1);
    }
}

__global__ void k_scan_a() {
    __shared__ int s[SCAN_B];
    int t = threadIdx.x;
    int i = blockIdx.x * SCAN_B + t;
    s[t] = (i < NN) ? g_deg[i] : 0;
    __syncthreads();
#pragma unroll
    for (int o = SCAN_B / 2; o > 0; o >>= 1) {
        if (t < o) s[t] += s[t + o];
        __syncthreads();
    }
    if (t == 0) g_part[blockIdx.x] = s[0];
}

__global__ void k_scan_b() {
    __shared__ int s[SCAN_B];
    int t = threadIdx.x;
    int v = (t < SCAN_G) ? g_part[t] : 0;
    s[t] = v;
    __syncthreads();
#pragma unroll
    for (int o = 1; o < SCAN_B; o <<= 1) {
        int u = (t >= o) ? s[t - o] : 0;
        __syncthreads();
        s[t] += u;
        __syncthreads();
    }
    if (t < SCAN_G) g_poff[t] = s[t] - v;
    if (t == SCAN_B - 1) g_off[NN] = s[SCAN_B - 1];
}

__global__ void k_scan_c() {
    __shared__ int s[SCAN_B];
    int t = threadIdx.x;
    int i = blockIdx.x * SCAN_B + t;
    int v = (i < NN) ? g_deg[i] : 0;
    s[t] = v;
    __syncthreads();
#pragma unroll
    for (int o = 1; o < SCAN_B; o <<= 1) {
        int u = (t >= o) ? s[t - o] : 0;
        __syncthreads();
        s[t] += u;
        __syncthreads();
    }
    if (i < NN) {
        int off = g_poff[blockIdx.x] + s[t] - v;
        g_off[i] = off;
        g_cur[i] = off;
        g_dinv[i] = rsqrtf((float)(v + 1));
    }
}

__global__ void k_scatter(const void* __restrict__ ei) {
    int e = blockIdx.x * blockDim.x + threadIdx.x;
    if (e < EE) {
        int d = edge_at(ei, (size_t)EE + e);
        int srcv = edge_at(ei, (size_t)e);
        if ((unsigned)d < NN && (unsigned)srcv < NN) {
            int pos = atomicAdd(&g_cur[d], 1);
            if ((unsigned)pos < EE) g_csr[pos] = srcv;
        }
    }
}

// ---------------- fp16 HMMA GEMM: full-tile smem, barrier-free k-loop --------
// C[m, col0+n] = A[m,:K] @ Wh[col0+n][:K]^T, half out. K <= 128.
// CVTA=1: A is external fp32 (converted during smem store). CVTA=0: A half.
// BM=128. 8 warps: warpM=w&3 (32 rows), warpN=w>>2 (NB/2 cols each).
#define LDS_H 136  // row stride in halves (272 B): conflict-free for ldmatrix
template <int NB, int CVTA>
__global__ void __launch_bounds__(256) k_gemm(const float* __restrict__ Af,
                                              int asel, int bsel, int csel,
                                              int M, int K, int ldc) {
    extern __shared__ __half smem[];
    __half* As = smem;                  // [128][LDS_H]
    __half* Bs = smem + 128 * LDS_H;    // [NB][LDS_H]
    const __half* __restrict__ A = pickA(asel);
    const __half* __restrict__ Wh = pickB(bsel);
    const int col0 = blockIdx.y * NB;
    const int row0 = blockIdx.x * 128;
    constexpr int FN = NB / 16;

    const int tid = threadIdx.x;
    const int lane = tid & 31;
    const int w = tid >> 5;
    const int warpM = w & 3;
    const int warpN = w >> 2;
    const int grp = lane >> 2;
    const int qid = lane & 3;

    const int k8 = K >> 3;
    // B panel
    for (int idx = tid; idx < NB * k8; idx += 256) {
        int r = idx / k8, c8 = idx - r * k8;
        *(uint4*)(Bs + r * LDS_H + c8 * 8) =
            *(const uint4*)(Wh + (size_t)(col0 + r) * K + c8 * 8);
    }
    // A panel (full 128 x K)
    for (int idx = tid; idx < 128 * k8; idx += 256) {
        int r = idx / k8, c8 = idx - r * k8;
        int gr = row0 + r;
        uint4 v;
        if (CVTA) {
            if (gr < M) {
                float4 f0 = *(const float4*)(Af + (size_t)gr * K + c8 * 8);
                float4 f1 = *(const float4*)(Af + (size_t)gr * K + c8 * 8 + 4);
                __half2 h[4] = {__floats2half2_rn(f0.x, f0.y),
                                __floats2half2_rn(f0.z, f0.w),
                                __floats2half2_rn(f1.x, f1.y),
                                __floats2half2_rn(f1.z, f1.w)};
                v = *(uint4*)h;
            } else {
                v = make_uint4(0, 0, 0, 0);
            }
        } else {
            v = (gr < M) ? *(const uint4*)(A + (size_t)gr * K + c8 * 8)
                         : make_uint4(0, 0, 0, 0);
        }
        *(uint4*)(As + r * LDS_H + c8 * 8) = v;
    }
    __syncthreads();

    const int arow = warpM * 32 + (lane & 7) + ((lane >> 3) & 1) * 8;
    const int acol = (lane >> 4) * 8;
    const int brow = warpN * (NB / 2) + ((lane >> 4)) * 8 + (lane & 7);
    const int bcol = ((lane >> 3) & 1) * 8;

    float acc[2][FN][4];
#pragma unroll
    for (int s = 0; s < 2; s++)
#pragma unroll
        for (int f = 0; f < FN; f++)
#pragma unroll
            for (int j = 0; j < 4; j++) acc[s][f][j] = 0.f;

    const int nit = K >> 4;
#pragma unroll 4
    for (int it = 0; it < nit; it++) {
        const int ko = it * 16;
        uint32_t av[2][4], bv[FN][2];
#pragma unroll
        for (int s = 0; s < 2; s++) {
            uint32_t addrA = (uint32_t)__cvta_generic_to_shared(
                As + (arow + s * 16) * LDS_H + acol + ko);
            ldsm_x4(av[s][0], av[s][1], av[s][2], av[s][3], addrA);
        }
#pragma unroll
        for (int p = 0; p < FN / 2; p++) {
            uint32_t addrB = (uint32_t)__cvta_generic_to_shared(
                Bs + (brow + p * 16) * LDS_H + bcol + ko);
            ldsm_x4(bv[2 * p][0], bv[2 * p][1], bv[2 * p + 1][0],
                    bv[2 * p + 1][1], addrB);
        }
#pragma unroll
        for (int s = 0; s < 2; s++)
#pragma unroll
            for (int f = 0; f < FN; f++) {
                asm volatile(
                    "mma.sync.aligned.m16n8k16.row.col.f32.f16.f16.f32 "
                    "{%0,%1,%2,%3}, {%4,%5,%6,%7}, {%8,%9}, {%0,%1,%2,%3};\n"
                    : "+f"(acc[s][f][0]), "+f"(acc[s][f][1]),
                      "+f"(acc[s][f][2]), "+f"(acc[s][f][3])
                    : "r"(av[s][0]), "r"(av[s][1]), "r"(av[s][2]),
                      "r"(av[s][3]), "r"(bv[f][0]), "r"(bv[f][1]));
            }
    }

    __half* Ch = pickC(csel);
#pragma unroll
    for (int s = 0; s < 2; s++) {
        int r0 = row0 + warpM * 32 + s * 16 + grp;
#pragma unroll
        for (int f = 0; f < FN; f++) {
            int c = col0 + warpN * (NB / 2) + f * 8 + 2 * qid;
            if (r0 < M)
                *(__half2*)(Ch + (size_t)r0 * ldc + c) =
                    __floats2half2_rn(acc[s][f][0], acc[s][f][1]);
            if (r0 + 8 < M)
                *(__half2*)(Ch + (size_t)(r0 + 8) * ldc + c) =
                    __floats2half2_rn(acc[s][f][2], acc[s][f][3]);
        }
    }
}

// ---------------- SAGE layer 1 aggregation + epilogue (relu) -----------------
// block (32,8): warp per node; lane t covers cols 4t..4t+3; unroll 8
__global__ void k_agg1(const float* __restrict__ b1l) {
    int i = blockIdx.x * 8 + threadIdx.y;
    if (i >= NN) return;
    int t = threadIdx.x;  // 0..31
    int off = g_off[i];
    int deg = g_deg[i];
    const uint2* base = (const uint2*)g_xlr;  // row = 64 uint2 (256 halves)
    float4 a0 = {0, 0, 0, 0}, a1 = a0, a2 = a0, a3 = a0;
    int j = 0;
    for (; j + 7 < deg; j += 8) {
        uint2 u0 = base[(size_t)g_csr[off + j] * 64 + t];
        uint2 u1 = base[(size_t)g_csr[off + j + 1] * 64 + t];
        uint2 u2 = base[(size_t)g_csr[off + j + 2] * 64 + t];
        uint2 u3 = base[(size_t)g_csr[off + j + 3] * 64 + t];
        uint2 u4 = base[(size_t)g_csr[off + j + 4] * 64 + t];
        uint2 u5 = base[(size_t)g_csr[off + j + 5] * 64 + t];
        uint2 u6 = base[(size_t)g_csr[off + j + 6] * 64 + t];
        uint2 u7 = base[(size_t)g_csr[off + j + 7] * 64 + t];
        float2 p, q;
        p = __half22float2(*(__half2*)&u0.x); q = __half22float2(*(__half2*)&u0.y);
        a0.x += p.x; a0.y += p.y; a0.z += q.x; a0.w += q.y;
        p = __half22float2(*(__half2*)&u1.x); q = __half22float2(*(__half2*)&u1.y);
        a1.x += p.x; a1.y += p.y; a1.z += q.x; a1.w += q.y;
        p = __half22float2(*(__half2*)&u2.x); q = __half22float2(*(__half2*)&u2.y);
        a2.x += p.x; a2.y += p.y; a2.z += q.x; a2.w += q.y;
        p = __half22float2(*(__half2*)&u3.x); q = __half22float2(*(__half2*)&u3.y);
        a3.x += p.x; a3.y += p.y; a3.z += q.x; a3.w += q.y;
        p = __half22float2(*(__half2*)&u4.x); q = __half22float2(*(__half2*)&u4.y);
        a0.x += p.x; a0.y += p.y; a0.z += q.x; a0.w += q.y;
        p = __half22float2(*(__half2*)&u5.x); q = __half22float2(*(__half2*)&u5.y);
        a1.x += p.x; a1.y += p.y; a1.z += q.x; a1.w += q.y;
        p = __half22float2(*(__half2*)&u6.x); q = __half22float2(*(__half2*)&u6.y);
        a2.x += p.x; a2.y += p.y; a2.z += q.x; a2.w += q.y;
        p = __half22float2(*(__half2*)&u7.x); q = __half22float2(*(__half2*)&u7.y);
        a3.x += p.x; a3.y += p.y; a3.z += q.x; a3.w += q.y;
    }
    for (; j < deg; j++) {
        uint2 u = base[(size_t)g_csr[off + j] * 64 + t];
        float2 p = __half22float2(*(__half2*)&u.x);
        float2 q = __half22float2(*(__half2*)&u.y);
        a0.x += p.x; a0.y += p.y; a0.z += q.x; a0.w += q.y;
    }
    float4 s;
    s.x = (a0.x + a1.x) + (a2.x + a3.x);
    s.y = (a0.y + a1.y) + (a2.y + a3.y);
    s.z = (a0.z + a1.z) + (a2.z + a3.z);
    s.w = (a0.w + a1.w) + (a2.w + a3.w);
    float inv = 1.f / fmaxf((float)deg, 1.f);
    uint2 ur = base[(size_t)i * 64 + 32 + t];
    float2 rp = __half22float2(*(__half2*)&ur.x);
    float2 rq = __half22float2(*(__half2*)&ur.y);
    float4 b = *(const float4*)(b1l + 4 * t);
    __half2 o0 = __floats2half2_rn(fmaxf(s.x * inv + b.x + rp.x, 0.f),
                                   fmaxf(s.y * inv + b.y + rp.y, 0.f));
    __half2 o1 = __floats2half2_rn(fmaxf(s.z * inv + b.z + rq.x, 0.f),
                                   fmaxf(s.w * inv + b.w + rq.y, 0.f));
    uint2 u;
    u.x = *(uint32_t*)&o0;
    u.y = *(uint32_t*)&o1;
    *(uint2*)(g_h + (size_t)i * 128 + 4 * t) = u;
}

// ---------------- SAGE layer 2 aggregation + softmax epilogue ----------------
__global__ void k_agg2(const float* __restrict__ b2l) {
    int i = blockIdx.x * 8 + threadIdx.y;
    if (i >= NN) return;
    int t = threadIdx.x;  // 0..31
    int off = g_off[i];
    int deg = g_deg[i];
    const __half2* base = (const __half2*)g_hlr;  // row stride 64 half2
    float2 a0 = {0, 0}, a1 = {0, 0}, a2 = {0, 0}, a3 = {0, 0};
    float2 a4 = {0, 0}, a5 = {0, 0}, a6 = {0, 0}, a7 = {0, 0};
    int j = 0;
    for (; j + 7 < deg; j += 8) {
        float2 v0 = __half22float2(base[(size_t)g_csr[off + j] * 64 + t]);
        float2 v1 = __half22float2(base[(size_t)g_csr[off + j + 1] * 64 + t]);
        float2 v2 = __half22float2(base[(size_t)g_csr[off + j + 2] * 64 + t]);
        float2 v3 = __half22float2(base[(size_t)g_csr[off + j + 3] * 64 + t]);
        float2 v4 = __half22float2(base[(size_t)g_csr[off + j + 4] * 64 + t]);
        float2 v5 = __half22float2(base[(size_t)g_csr[off + j + 5] * 64 + t]);
        float2 v6 = __half22float2(base[(size_t)g_csr[off + j + 6] * 64 + t]);
        float2 v7 = __half22float2(base[(size_t)g_csr[off + j + 7] * 64 + t]);
        a0.x += v0.x; a0.y += v0.y;  a1.x += v1.x; a1.y += v1.y;
        a2.x += v2.x; a2.y += v2.y;  a3.x += v3.x; a3.y += v3.y;
        a4.x += v4.x; a4.y += v4.y;  a5.x += v5.x; a5.y += v5.y;
        a6.x += v6.x; a6.y += v6.y;  a7.x += v7.x; a7.y += v7.y;
    }
    for (; j < deg; j++) {
        float2 v = __half22float2(base[(size_t)g_csr[off + j] * 64 + t]);
        a0.x += v.x; a0.y += v.y;
    }
    float sx = ((a0.x + a1.x) + (a2.x + a3.x)) + ((a4.x + a5.x) + (a6.x + a7.x));
    float sy = ((a0.y + a1.y) + (a2.y + a3.y)) + ((a4.y + a5.y) + (a6.y + a7.y));
    float inv = 1.f / fmaxf((float)deg, 1.f);
    float2 hr = __half22float2(base[(size_t)i * 64 + 32 + t]);
    float v0 = sx * inv + b2l[2 * t] + hr.x;
    float v1 = sy * inv + b2l[2 * t + 1] + hr.y;
    float m = fmaxf(v0, v1);
#pragma unroll
    for (int o = 16; o > 0; o >>= 1) m = fmaxf(m, __shfl_xor_sync(0xffffffffu, m, o));
    float e0 = __expf(v0 - m), e1 = __expf(v1 - m);
    float s = e0 + e1;
#pragma unroll
    for (int o = 16; o > 0; o >>= 1) s += __shfl_xor_sync(0xffffffffu, s, o);
    float rs = 1.f / s;
    *(__half2*)(g_h3 + (size_t)i * 64 + 2 * t) =
        __floats2half2_rn(e0 * rs, e1 * rs);
}

// ---------------- GCN aggregation (writes final output) ----------------------
__global__ void k_agg3(const float* __restrict__ bg, float* __restrict__ out) {
    int i = blockIdx.x * 8 + threadIdx.y;
    if (i >= NN) return;
    int t = threadIdx.x;  // 0..31
    int off = g_off[i];
    int deg = g_deg[i];
    float di = g_dinv[i];
    const __half2* base = (const __half2*)g_xw;  // row stride 32 half2
    float2 a0 = {0, 0}, a1 = {0, 0}, a2 = {0, 0}, a3 = {0, 0};
    float2 a4 = {0, 0}, a5 = {0, 0}, a6 = {0, 0}, a7 = {0, 0};
    int j = 0;
    for (; j + 7 < deg; j += 8) {
        int s0 = g_csr[off + j],     s1 = g_csr[off + j + 1];
        int s2 = g_csr[off + j + 2], s3 = g_csr[off + j + 3];
        int s4 = g_csr[off + j + 4], s5 = g_csr[off + j + 5];
        int s6 = g_csr[off + j + 6], s7 = g_csr[off + j + 7];
        float d0 = g_dinv[s0], d1 = g_dinv[s1], d2 = g_dinv[s2], d3 = g_dinv[s3];
        float d4 = g_dinv[s4], d5 = g_dinv[s5], d6 = g_dinv[s6], d7 = g_dinv[s7];
        float2 v0 = __half22float2(base[(size_t)s0 * 32 + t]);
        float2 v1 = __half22float2(base[(size_t)s1 * 32 + t]);
        float2 v2 = __half22float2(base[(size_t)s2 * 32 + t]);
        float2 v3 = __half22float2(base[(size_t)s3 * 32 + t]);
        float2 v4 = __half22float2(base[(size_t)s4 * 32 + t]);
        float2 v5 = __half22float2(base[(size_t)s5 * 32 + t]);
        float2 v6 = __half22float2(base[(size_t)s6 * 32 + t]);
        float2 v7 = __half22float2(base[(size_t)s7 * 32 + t]);
        a0.x += v0.x * d0; a0.y += v0.y * d0;
        a1.x += v1.x * d1; a1.y += v1.y * d1;
        a2.x += v2.x * d2; a2.y += v2.y * d2;
        a3.x += v3.x * d3; a3.y += v3.y * d3;
        a4.x += v4.x * d4; a4.y += v4.y * d4;
        a5.x += v5.x * d5; a5.y += v5.y * d5;
        a6.x += v6.x * d6; a6.y += v6.y * d6;
        a7.x += v7.x * d7; a7.y += v7.y * d7;
    }
    for (; j < deg; j++) {
        int s = g_csr[off + j];
        float d = g_dinv[s];
        float2 v = __half22float2(base[(size_t)s * 32 + t]);
        a0.x += v.x * d; a0.y += v.y * d;
    }
    float2 self = __half22float2(base[(size_t)i * 32 + t]);
    float sx = ((a0.x + a1.x) + (a2.x + a3.x)) + ((a4.x + a5.x) + (a6.x + a7.x)) +
               self.x * di;
    float sy = ((a0.y + a1.y) + (a2.y + a3.y)) + ((a4.y + a5.y) + (a6.y + a7.y)) +
               self.y * di;
    float ox = sx * di + bg[2 * t];
    float oy = sy * di + bg[2 * t + 1];
    *(float2*)(out + (size_t)i * 64 + 2 * t) = make_float2(ox, oy);
}

// ---------------- launch -----------------------------------------------------
extern "C" void kernel_launch(void* const* d_in, const int* in_sizes, int n_in,
                              void* d_out, int out_size) {
    const float* x = (const float*)d_in[0];
    const void* ei = d_in[1];
    const float* W1l = (const float*)d_in[2];
    const float* b1l = (const float*)d_in[3];
    const float* W1r = (const float*)d_in[4];
    const float* W2l = (const float*)d_in[5];
    const float* b2l = (const float*)d_in[6];
    const float* W2r = (const float*)d_in[7];
    const float* Wg = (const float*)d_in[8];
    const float* bg = (const float*)d_in[9];
    float* out = (float*)d_out;

    const int smem128 = (128 + 128) * LDS_H * 2;  // 69632 B
    const int smem64 = (128 + 64) * LDS_H * 2;    // 52224 B
    cudaFuncSetAttribute(k_gemm<128, 1>,
                         cudaFuncAttributeMaxDynamicSharedMemorySize, smem128);
    cudaFuncSetAttribute(k_gemm<128, 0>,
                         cudaFuncAttributeMaxDynamicSharedMemorySize, smem128);
    cudaFuncSetAttribute(k_gemm<64, 0>,
                         cudaFuncAttributeMaxDynamicSharedMemorySize, smem64);

    k_init<<<INIT_G, SCAN_B>>>(ei, W1l, W1r, W2l, W2r, Wg);
    k_hist<<<(EE + 255) / 256, 256>>>(ei);
    // gemm1 (fp32 A, converts in-kernel): [xl|xr] = x @ [W1l,W1r], BN=128
    dim3 g1((NN + 127) / 128, 2);
    k_gemm<128, 1><<<g1, 256, smem128>>>(x, 0, 0, 0, NN, 128, 256);
    k_scan_a<<<SCAN_G, SCAN_B>>>();
    k_scan_b<<<1, SCAN_B>>>();
    k_scan_c<<<SCAN_G, SCAN_B>>>();
    k_scatter<<<(EE + 255) / 256, 256>>>(ei);
    k_agg1<<<(NN + 7) / 8, dim3(32, 8)>>>(b1l);
    dim3 g2((NN + 127) / 128, 1);
    k_gemm<128, 0><<<g2, 256, smem128>>>(nullptr, 1, 1, 1, NN, 128, 128);
    k_agg2<<<(NN + 7) / 8, dim3(32, 8)>>>(b2l);
    dim3 g3((NN + 127) / 128, 1);
    k_gemm<64, 0><<<g3, 256, smem64>>>(nullptr, 2, 2, 2, NN, 64, 64);
    k_agg3<<<(NN + 7) / 8, dim3(32, 8)>>>(bg, out);
}